// round 2
// baseline (speedup 1.0000x reference)
#include <cuda_runtime.h>
#include <math.h>

#define BB 256
#define LL 1024
#define TT 64

// Per-(batch, step) forward scaling factors rho_l. (B, L) layout. 1 MB static.
__device__ float g_rho[BB * LL];

__device__ __forceinline__ float warp_sum(float v) {
    v += __shfl_xor_sync(0xffffffffu, v, 16);
    v += __shfl_xor_sync(0xffffffffu, v, 8);
    v += __shfl_xor_sync(0xffffffffu, v, 4);
    v += __shfl_xor_sync(0xffffffffu, v, 2);
    v += __shfl_xor_sync(0xffffffffu, v, 1);
    return v;
}

// ---------------------------------------------------------------------------
// Forward (Rabiner-scaled):
//   s_0[k] = exp(em_0[k] + start[k])
//   rho_l  = sum_k s_{l-1}[k]
//   s_l[k] = (sum_j s_{l-1}[j] * E[j,k]) * exp(em_l[k]) / rho_l   (E = exp(trans))
// Stores s_l into alphaS (= d_out scratch) and rho_l into g_rho.
// ---------------------------------------------------------------------------
__global__ __launch_bounds__(64) void crf_forward(
    const float* __restrict__ em,     // (B, L, T)
    const float* __restrict__ start,  // (T)
    const float* __restrict__ trans,  // (T, T)
    const int*   __restrict__ mask,   // (B, L)
    float* __restrict__ alphaS)       // (L, B, T)
{
    const int b = blockIdx.x;
    const int k = threadIdx.x;
    const int w = k >> 5;

    __shared__ float sh[2][TT];
    __shared__ float shw[2][2];
    __shared__ int   shm[LL];

    for (int i = k; i < LL; i += 64) shm[i] = mask[b * LL + i];

    // exp(trans) column k -> registers
    float col[TT];
#pragma unroll
    for (int j = 0; j < TT; ++j) col[j] = expf(trans[j * TT + k]);

    const float* emb = em + (size_t)b * LL * TT + k;

    float s = expf(emb[0] + start[k]);
    alphaS[(size_t)b * TT + k] = s;   // l = 0

    __syncthreads();  // mask staging done

    // prefetch em for steps l = 1..4
    float ebuf[4];
#pragma unroll
    for (int u = 0; u < 4; ++u) {
        int ln = 1 + u;
        ebuf[u] = (ln < LL) ? emb[(size_t)ln * TT] : 0.f;
    }

    for (int l0 = 1; l0 < LL; l0 += 4) {
        float enext[4];
#pragma unroll
        for (int u = 0; u < 4; ++u) {
            int ln = l0 + 4 + u;
            enext[u] = (ln < LL) ? emb[(size_t)ln * TT] : 0.f;
        }
#pragma unroll
        for (int u = 0; u < 4; ++u) {
            int l = l0 + u;
            if (l < LL) {
                int buf = l & 1;
                sh[buf][k] = s;
                float rs = warp_sum(s);
                if ((k & 31) == 0) shw[buf][w] = rs;
                __syncthreads();
                float r = shw[buf][0] + shw[buf][1];
                const float4* sv = (const float4*)sh[buf];
                float q0 = 0.f, q1 = 0.f, q2 = 0.f, q3 = 0.f;
#pragma unroll
                for (int j4 = 0; j4 < 16; ++j4) {
                    float4 v = sv[j4];
                    q0 = fmaf(v.x, col[4 * j4 + 0], q0);
                    q1 = fmaf(v.y, col[4 * j4 + 1], q1);
                    q2 = fmaf(v.z, col[4 * j4 + 2], q2);
                    q3 = fmaf(v.w, col[4 * j4 + 3], q3);
                }
                float q = (q0 + q1) + (q2 + q3);
                float e = expf(ebuf[u]);
                if (shm[l]) {
                    s = (q / r) * e;
                }
                alphaS[(size_t)l * BB * TT + b * TT + k] = s;
                if (k == 0) g_rho[b * LL + l] = r;
            }
        }
#pragma unroll
        for (int u = 0; u < 4; ++u) ebuf[u] = enext[u];
    }
}

// ---------------------------------------------------------------------------
// Backward + combine (Rabiner-scaled with the FORWARD scalars rho_l):
//   b_{L-1}[j] = exp(end[j])
//   b_{l-1}[j] = (sum_k E[j,k] * exp(em_l[k]) * b_l[k]) / rho_l
//   zh = sum_k s_{L-1}[k] * exp(end[k])
//   out[l,b,k] = s_l[k] * b_l[k] / zh          (everything O(1), no logs)
// Overwrites alphaS in place.
// ---------------------------------------------------------------------------
__global__ __launch_bounds__(64) void crf_backward(
    const float* __restrict__ em,     // (B, L, T)
    const float* __restrict__ endt,   // (T)
    const float* __restrict__ trans,  // (T, T)
    const int*   __restrict__ mask,   // (B, L)
    float* __restrict__ outA)         // (L, B, T): in = s_alpha, out = result
{
    const int b = blockIdx.x;
    const int j = threadIdx.x;
    const int w = j >> 5;

    __shared__ float sh[2][TT];
    __shared__ float shw[2];
    __shared__ int   shm[LL];
    __shared__ float shr[LL];

    for (int i = j; i < LL; i += 64) shm[i] = mask[b * LL + i];
    for (int i = j; i < LL; i += 64) shr[i] = g_rho[b * LL + i];

    // exp(trans) row j -> registers
    float row[TT];
#pragma unroll
    for (int i = 0; i < TT; ++i) row[i] = expf(trans[j * TT + i]);

    float eEnd = expf(endt[j]);

    const float* emb  = em   + (size_t)b * LL * TT + j;
    float*       outb = outA + (size_t)b * TT + j;   // + l*B*T

    __syncthreads();  // staging done

    // zh = sum_k s_{L-1}[k] * exp(end[k])
    float term = outb[(size_t)(LL - 1) * BB * TT] * eEnd;
    float ts = warp_sum(term);
    if ((j & 31) == 0) shw[w] = ts;
    __syncthreads();
    float inv_z = 1.f / (shw[0] + shw[1]);

    float sb = eEnd;

    // prefetch for l = L-1 .. L-4 (descending)
    float ebuf[4], abuf[4];
#pragma unroll
    for (int u = 0; u < 4; ++u) {
        int l = (LL - 1) - u;
        ebuf[u] = (l >= 0) ? emb[(size_t)l * TT] : 0.f;
        abuf[u] = (l >= 0) ? outb[(size_t)l * BB * TT] : 0.f;
    }

    for (int l0 = LL - 1; l0 >= 0; l0 -= 4) {
        float enext[4], anext[4];
#pragma unroll
        for (int u = 0; u < 4; ++u) {
            int ln = l0 - 4 - u;
            enext[u] = (ln >= 0) ? emb[(size_t)ln * TT] : 0.f;
            anext[u] = (ln >= 0) ? outb[(size_t)ln * BB * TT] : 0.f;
        }
#pragma unroll
        for (int u = 0; u < 4; ++u) {
            int l = l0 - u;
            if (l >= 0) {
                // combine for position l using current b_hat (sb)
                float o = abuf[u] * sb * inv_z;
                outb[(size_t)l * BB * TT] = o;

                if (l > 0) {
                    // t[k] = exp(em_l[k]) * b_l[k]  (this thread's tag = j)
                    float t = sb * expf(ebuf[u]);
                    int buf = l & 1;
                    sh[buf][j] = t;
                    __syncthreads();
                    const float4* sv = (const float4*)sh[buf];
                    float q0 = 0.f, q1 = 0.f, q2 = 0.f, q3 = 0.f;
#pragma unroll
                    for (int i4 = 0; i4 < 16; ++i4) {
                        float4 v = sv[i4];
                        q0 = fmaf(v.x, row[4 * i4 + 0], q0);
                        q1 = fmaf(v.y, row[4 * i4 + 1], q1);
                        q2 = fmaf(v.z, row[4 * i4 + 2], q2);
                        q3 = fmaf(v.w, row[4 * i4 + 3], q3);
                    }
                    float q = (q0 + q1) + (q2 + q3);
                    if (shm[l]) {
                        sb = q / shr[l];
                    }
                }
            }
        }
#pragma unroll
        for (int u = 0; u < 4; ++u) { ebuf[u] = enext[u]; abuf[u] = anext[u]; }
    }
}

extern "C" void kernel_launch(void* const* d_in, const int* in_sizes, int n_in,
                              void* d_out, int out_size) {
    const float* em    = (const float*)d_in[0];  // emissions (B,L,T)
    const float* start = (const float*)d_in[1];  // start_transitions (T)
    const float* endt  = (const float*)d_in[2];  // end_transitions (T)
    const float* trans = (const float*)d_in[3];  // transitions (T,T)
    const int*   mask  = (const int*)d_in[4];    // mask (B,L)
    float* out = (float*)d_out;                  // (L,B,T)

    crf_forward<<<BB, TT>>>(em, start, trans, mask, out);
    crf_backward<<<BB, TT>>>(em, endt, trans, mask, out);
}

// round 3
// speedup vs baseline: 1.1166x; 1.1166x over previous
#include <cuda_runtime.h>
#include <math.h>

#define BB 256
#define LL 1024
#define TT 64

// Scaled backward vectors (L, B, T). 64 MB static device scratch.
__device__ float g_sB[(size_t)LL * BB * TT];

// ---- packed f32x2 helpers (sm_103a) ----
#define FMA_F32X2(d, a, b, c) \
    asm("fma.rn.f32x2 %0, %1, %2, %3;" : "=l"(d) : "l"(a), "l"(b), "l"(c))
#define ADD_F32X2(d, a, b) \
    asm("add.rn.f32x2 %0, %1, %2;" : "=l"(d) : "l"(a), "l"(b))

__device__ __forceinline__ unsigned long long pack2(float lo, float hi) {
    unsigned long long r;
    asm("mov.b64 %0, {%1, %2};" : "=l"(r)
        : "r"(__float_as_uint(lo)), "r"(__float_as_uint(hi)));
    return r;
}
__device__ __forceinline__ float unpack_sum(unsigned long long v) {
    unsigned int lo, hi;
    asm("mov.b64 {%0, %1}, %2;" : "=r"(lo), "=r"(hi) : "l"(v));
    return __uint_as_float(lo) + __uint_as_float(hi);
}

__device__ __forceinline__ float warp_sum(float v) {
    v += __shfl_xor_sync(0xffffffffu, v, 16);
    v += __shfl_xor_sync(0xffffffffu, v, 8);
    v += __shfl_xor_sync(0xffffffffu, v, 4);
    v += __shfl_xor_sync(0xffffffffu, v, 2);
    v += __shfl_xor_sync(0xffffffffu, v, 1);
    return v;
}

// Packed matvec: q = sum over 64 of sh[j]*w2[j/2 packed], w2 = 32 packed pairs.
__device__ __forceinline__ float matvec64(const float* sh,
                                          const unsigned long long* w2) {
    const ulonglong2* sv = (const ulonglong2*)sh;  // broadcast reads
    unsigned long long qa = 0ull, qb = 0ull, qc = 0ull, qd = 0ull;
#pragma unroll
    for (int t = 0; t < 16; t += 2) {
        ulonglong2 v0 = sv[t];
        ulonglong2 v1 = sv[t + 1];
        FMA_F32X2(qa, v0.x, w2[2 * t + 0], qa);
        FMA_F32X2(qb, v0.y, w2[2 * t + 1], qb);
        FMA_F32X2(qc, v1.x, w2[2 * t + 2], qc);
        FMA_F32X2(qd, v1.y, w2[2 * t + 3], qd);
    }
    ADD_F32X2(qa, qa, qc);
    ADD_F32X2(qb, qb, qd);
    ADD_F32X2(qa, qa, qb);
    return unpack_sum(qa);
}

// ---------------------------------------------------------------------------
// Fused scan: blocks [0,B) run the forward recursion (own Rabiner scaling),
// blocks [B,2B) run the backward recursion (own, independent scaling).
// Forward writes sA into d_out; backward writes sB into g_sB.
// A later combine normalizes per (l,b): out = sA*sB / sum_k(sA*sB).
// ---------------------------------------------------------------------------
__global__ __launch_bounds__(64) void crf_scan(
    const float* __restrict__ em,     // (B, L, T)
    const float* __restrict__ start,  // (T)
    const float* __restrict__ endt,   // (T)
    const float* __restrict__ trans,  // (T, T)
    const int*   __restrict__ mask,   // (B, L)
    float* __restrict__ sA)           // (L, B, T) = d_out
{
    const int k = threadIdx.x;        // this thread's tag
    const int w = k >> 5;

    __shared__ __align__(16) float sh[2][TT];
    __shared__ float shw[2][2];
    __shared__ int   shm[LL];

    if (blockIdx.x < BB) {
        // ================= FORWARD =================
        const int b = blockIdx.x;
        for (int i = k; i < LL; i += 64) shm[i] = mask[b * LL + i];

        // E column k, packed over j
        unsigned long long col2[TT / 2];
#pragma unroll
        for (int j2 = 0; j2 < TT / 2; ++j2)
            col2[j2] = pack2(expf(trans[(2 * j2) * TT + k]),
                             expf(trans[(2 * j2 + 1) * TT + k]));

        const float* emb = em + (size_t)b * LL * TT + k;

        float s = expf(emb[0] + start[k]);
        sA[(size_t)b * TT + k] = s;  // l = 0
        __syncthreads();

        float ebuf[4];
#pragma unroll
        for (int u = 0; u < 4; ++u)
            ebuf[u] = expf(emb[(size_t)(1 + u) * TT]);

        for (int l0 = 1; l0 < LL; l0 += 4) {
            float enext[4];
#pragma unroll
            for (int u = 0; u < 4; ++u) {
                int ln = l0 + 4 + u;
                enext[u] = (ln < LL) ? expf(emb[(size_t)ln * TT]) : 0.f;
            }
#pragma unroll
            for (int u = 0; u < 4; ++u) {
                int l = l0 + u;
                if (l < LL) {
                    int buf = l & 1;
                    sh[buf][k] = s;
                    float rs = warp_sum(s);
                    if ((k & 31) == 0) shw[buf][w] = rs;
                    __syncthreads();
                    float inv_r = 1.f / (shw[buf][0] + shw[buf][1]);
                    float q = matvec64(sh[buf], col2);
                    if (shm[l]) s = q * inv_r * ebuf[u];
                    sA[(size_t)l * BB * TT + b * TT + k] = s;
                }
            }
#pragma unroll
            for (int u = 0; u < 4; ++u) ebuf[u] = enext[u];
        }
    } else {
        // ================= BACKWARD =================
        const int b = blockIdx.x - BB;
        const int j = k;
        for (int i = j; i < LL; i += 64) shm[i] = mask[b * LL + i];

        // E row j, packed over i
        unsigned long long row2[TT / 2];
#pragma unroll
        for (int i2 = 0; i2 < TT / 2; ++i2)
            row2[i2] = pack2(expf(trans[j * TT + 2 * i2]),
                             expf(trans[j * TT + 2 * i2 + 1]));

        const float* emb = em + (size_t)b * LL * TT + j;

        float sb = expf(endt[j]);
        g_sB[(size_t)(LL - 1) * BB * TT + b * TT + j] = sb;  // l = L-1
        __syncthreads();

        float ebuf[4];
#pragma unroll
        for (int u = 0; u < 4; ++u)
            ebuf[u] = expf(emb[(size_t)(LL - 1 - u) * TT]);

        for (int l0 = LL - 1; l0 >= 1; l0 -= 4) {
            float enext[4];
#pragma unroll
            for (int u = 0; u < 4; ++u) {
                int ln = l0 - 4 - u;
                enext[u] = (ln >= 1) ? expf(emb[(size_t)ln * TT]) : 0.f;
            }
#pragma unroll
            for (int u = 0; u < 4; ++u) {
                int l = l0 - u;
                if (l >= 1) {
                    // t[k] = exp(em_l[k]) * b_l[k]
                    float t = sb * ebuf[u];
                    int buf = l & 1;
                    sh[buf][j] = t;
                    float rs = warp_sum(t);
                    if ((j & 31) == 0) shw[buf][w] = rs;
                    __syncthreads();
                    float inv_r = 1.f / (shw[buf][0] + shw[buf][1]);
                    float q = matvec64(sh[buf], row2);
                    if (shm[l]) sb = q * inv_r;
                    g_sB[(size_t)(l - 1) * BB * TT + b * TT + j] = sb;
                }
            }
#pragma unroll
            for (int u = 0; u < 4; ++u) ebuf[u] = enext[u];
        }
    }
}

// ---------------------------------------------------------------------------
// Combine: out[p, k] = sA[p,k]*sB[p,k] / sum_k(sA[p,k]*sB[p,k]),
// p = (l, b) flattened. 4 positions per 256-thread block (64-thread tiles).
// ---------------------------------------------------------------------------
__global__ __launch_bounds__(256) void crf_combine(
    float* __restrict__ outA)   // (L*B, T): in = sA, out = marginals
{
    const int tile = threadIdx.x >> 6;     // 0..3
    const int k    = threadIdx.x & 63;
    const int wloc = (threadIdx.x >> 5) & 1;
    const size_t p = (size_t)blockIdx.x * 4 + tile;

    __shared__ float sw[8];

    const size_t idx = p * TT + k;
    float v = outA[idx] * g_sB[idx];
    float rs = warp_sum(v);
    if ((k & 31) == 0) sw[2 * tile + wloc] = rs;
    __syncthreads();
    float inv = 1.f / (sw[2 * tile] + sw[2 * tile + 1]);
    outA[idx] = v * inv;
}

extern "C" void kernel_launch(void* const* d_in, const int* in_sizes, int n_in,
                              void* d_out, int out_size) {
    const float* em    = (const float*)d_in[0];  // emissions (B,L,T)
    const float* start = (const float*)d_in[1];  // start_transitions (T)
    const float* endt  = (const float*)d_in[2];  // end_transitions (T)
    const float* trans = (const float*)d_in[3];  // transitions (T,T)
    const int*   mask  = (const int*)d_in[4];    // mask (B,L)
    float* out = (float*)d_out;                  // (L,B,T)

    crf_scan<<<2 * BB, TT>>>(em, start, endt, trans, mask, out);
    crf_combine<<<(LL * BB) / 4, 256>>>(out);
}